// round 5
// baseline (speedup 1.0000x reference)
#include <cuda_runtime.h>
#include <stdint.h>

#define N_NODES 100000
#define N_EDGES 600000
#define D 128
#define H 256
#define TILE_M 128
#define NTILES ((N_NODES + TILE_M - 1) / TILE_M)   // 782

#define LDX 132   // smem row stride (floats) for 128-col X tile  -> (4r+k)%32 perfect
#define LDH 260   // smem row stride (floats) for 256-col tiles   -> (4r+k)%32 perfect

// Scratch (allocation-free rule: device globals)
__device__ float g_m[(size_t)N_NODES * D];
__device__ float g_agg[(size_t)N_NODES * D];

// ---------------------------------------------------------------------------
// helpers
// ---------------------------------------------------------------------------
__device__ __forceinline__ uint32_t f2tf(float f) {
    uint32_t u;
    asm("cvt.rna.tf32.f32 %0, %1;" : "=r"(u) : "f"(f));
    return u;
}

__device__ __forceinline__ void mma_tf32(float c[4], const uint32_t a[4], const uint32_t b[2]) {
    asm volatile(
        "mma.sync.aligned.m16n8k8.row.col.f32.tf32.tf32.f32 "
        "{%0,%1,%2,%3}, {%4,%5,%6,%7}, {%8,%9}, {%0,%1,%2,%3};\n"
        : "+f"(c[0]), "+f"(c[1]), "+f"(c[2]), "+f"(c[3])
        : "r"(a[0]), "r"(a[1]), "r"(a[2]), "r"(a[3]),
          "r"(b[0]), "r"(b[1]));
}

// ---------------------------------------------------------------------------
// Kernel 1: m = relu(X @ Wm1 + bm1) @ Wm2 + bm2         (per 128-row tile)
// ---------------------------------------------------------------------------
__global__ __launch_bounds__(256, 1)
void msg_mlp_kernel(const float* __restrict__ nodes,
                    const float* __restrict__ Wm1, const float* __restrict__ bm1,
                    const float* __restrict__ Wm2, const float* __restrict__ bm2)
{
    extern __shared__ uint32_t smem[];
    uint32_t* sX = smem;                    // [128][LDX] tf32 bits
    uint32_t* sH = smem + TILE_M * LDX;     // [128][LDH] tf32 bits

    const int row0 = blockIdx.x * TILE_M;
    const int tid  = threadIdx.x;
    const int warp = tid >> 5;
    const int lane = tid & 31;
    const int lq   = lane >> 2;   // 0..7
    const int lr   = lane & 3;    // 0..3

    // stage X tile (zero-padded tail rows), converting fp32 -> tf32 once
    for (int i = tid; i < TILE_M * (D / 4); i += 256) {
        int r  = i >> 5;            // 32 float4 per row
        int c4 = (i & 31) * 4;
        float4 v = make_float4(0.f, 0.f, 0.f, 0.f);
        int gr = row0 + r;
        if (gr < N_NODES) v = *reinterpret_cast<const float4*>(nodes + (size_t)gr * D + c4);
        uint32_t* dst = sX + r * LDX + c4;
        dst[0] = f2tf(v.x); dst[1] = f2tf(v.y); dst[2] = f2tf(v.z); dst[3] = f2tf(v.w);
    }
    __syncthreads();

    // ---- GEMM1: hidden[128x256]; warp owns cols [warp*32, warp*32+32)
    {
        float acc[8][4][4];
        #pragma unroll
        for (int i = 0; i < 8; ++i)
            #pragma unroll
            for (int j = 0; j < 4; ++j)
                #pragma unroll
                for (int k = 0; k < 4; ++k) acc[i][j][k] = 0.f;

        const int ncol0 = warp * 32;
        #pragma unroll 1
        for (int kt = 0; kt < D / 8; ++kt) {
            const int kb = kt * 8;
            uint32_t b[4][2];
            #pragma unroll
            for (int ct = 0; ct < 4; ++ct) {
                int n = ncol0 + ct * 8 + lq;
                b[ct][0] = f2tf(__ldg(Wm1 + (size_t)(kb + lr) * H + n));
                b[ct][1] = f2tf(__ldg(Wm1 + (size_t)(kb + 4 + lr) * H + n));
            }
            #pragma unroll
            for (int rt = 0; rt < 8; ++rt) {
                const uint32_t* base = sX + (rt * 16 + lq) * LDX + kb + lr;
                uint32_t a[4];
                a[0] = base[0];
                a[1] = base[8 * LDX];
                a[2] = base[4];
                a[3] = base[8 * LDX + 4];
                #pragma unroll
                for (int ct = 0; ct < 4; ++ct) mma_tf32(acc[rt][ct], a, b[ct]);
            }
        }
        // bias + relu -> sH (tf32)
        #pragma unroll
        for (int rt = 0; rt < 8; ++rt) {
            #pragma unroll
            for (int ct = 0; ct < 4; ++ct) {
                int r = rt * 16 + lq;
                int c = ncol0 + ct * 8 + lr * 2;
                float b0 = __ldg(bm1 + c), b1 = __ldg(bm1 + c + 1);
                sH[r * LDH + c]           = f2tf(fmaxf(acc[rt][ct][0] + b0, 0.f));
                sH[r * LDH + c + 1]       = f2tf(fmaxf(acc[rt][ct][1] + b1, 0.f));
                sH[(r + 8) * LDH + c]     = f2tf(fmaxf(acc[rt][ct][2] + b0, 0.f));
                sH[(r + 8) * LDH + c + 1] = f2tf(fmaxf(acc[rt][ct][3] + b1, 0.f));
            }
        }
    }
    __syncthreads();

    // ---- GEMM2: m[128x128] = hidden @ Wm2 + bm2; warps in 2x4 grid
    {
        const int wr = warp >> 2;   // 0..1 -> rows wr*64
        const int wc = warp & 3;    // 0..3 -> cols wc*32
        float acc[4][4][4];
        #pragma unroll
        for (int i = 0; i < 4; ++i)
            #pragma unroll
            for (int j = 0; j < 4; ++j)
                #pragma unroll
                for (int k = 0; k < 4; ++k) acc[i][j][k] = 0.f;

        #pragma unroll 1
        for (int kt = 0; kt < H / 8; ++kt) {
            const int kb = kt * 8;
            uint32_t b[4][2];
            #pragma unroll
            for (int ct = 0; ct < 4; ++ct) {
                int n = wc * 32 + ct * 8 + lq;
                b[ct][0] = f2tf(__ldg(Wm2 + (size_t)(kb + lr) * D + n));
                b[ct][1] = f2tf(__ldg(Wm2 + (size_t)(kb + 4 + lr) * D + n));
            }
            #pragma unroll
            for (int rt = 0; rt < 4; ++rt) {
                const uint32_t* base = sH + (wr * 64 + rt * 16 + lq) * LDH + kb + lr;
                uint32_t a[4];
                a[0] = base[0];
                a[1] = base[8 * LDH];
                a[2] = base[4];
                a[3] = base[8 * LDH + 4];
                #pragma unroll
                for (int ct = 0; ct < 4; ++ct) mma_tf32(acc[rt][ct], a, b[ct]);
            }
        }
        #pragma unroll
        for (int rt = 0; rt < 4; ++rt) {
            #pragma unroll
            for (int ct = 0; ct < 4; ++ct) {
                int r = wr * 64 + rt * 16 + lq;
                int c = wc * 32 + ct * 8 + lr * 2;
                float b0 = __ldg(bm2 + c), b1 = __ldg(bm2 + c + 1);
                int gr = row0 + r;
                if (gr < N_NODES) {
                    float2 v = make_float2(acc[rt][ct][0] + b0, acc[rt][ct][1] + b1);
                    *reinterpret_cast<float2*>(g_m + (size_t)gr * D + c) = v;
                }
                int gr2 = gr + 8;
                if (gr2 < N_NODES) {
                    float2 v = make_float2(acc[rt][ct][2] + b0, acc[rt][ct][3] + b1);
                    *reinterpret_cast<float2*>(g_m + (size_t)gr2 * D + c) = v;
                }
            }
        }
    }
}

// ---------------------------------------------------------------------------
// Kernel 2a: zero agg
// ---------------------------------------------------------------------------
__global__ void zero_agg_kernel()
{
    size_t i = (size_t)blockIdx.x * blockDim.x + threadIdx.x;
    size_t n4 = (size_t)N_NODES * D / 4;
    if (i < n4)
        reinterpret_cast<float4*>(g_agg)[i] = make_float4(0.f, 0.f, 0.f, 0.f);
}

// ---------------------------------------------------------------------------
// Kernel 2b: agg[recv] += m[send]   (one warp per edge, vector red to L2)
// ---------------------------------------------------------------------------
__global__ __launch_bounds__(256)
void scatter_kernel(const int* __restrict__ senders, const int* __restrict__ receivers)
{
    int e = (blockIdx.x * 256 + threadIdx.x) >> 5;
    int lane = threadIdx.x & 31;
    if (e >= N_EDGES) return;
    int s = __ldg(senders + e);
    int r = __ldg(receivers + e);
    float4 v = *reinterpret_cast<const float4*>(g_m + (size_t)s * D + lane * 4);
    float* dst = g_agg + (size_t)r * D + lane * 4;
    asm volatile("red.global.add.v4.f32 [%0], {%1,%2,%3,%4};"
                 :: "l"(dst), "f"(v.x), "f"(v.y), "f"(v.z), "f"(v.w)
                 : "memory");
}

// ---------------------------------------------------------------------------
// Kernel 3: out = nodes + relu([nodes||agg] @ Wn1 + bn1) @ Wn2 + bn2
// ---------------------------------------------------------------------------
__global__ __launch_bounds__(256, 1)
void node_mlp_kernel(const float* __restrict__ nodes,
                     const float* __restrict__ Wn1, const float* __restrict__ bn1,
                     const float* __restrict__ Wn2, const float* __restrict__ bn2,
                     float* __restrict__ out)
{
    extern __shared__ uint32_t smem[];
    uint32_t* sA = smem;   // [128][LDH]; first A = [X||agg], later reused as hidden

    const int row0 = blockIdx.x * TILE_M;
    const int tid  = threadIdx.x;
    const int warp = tid >> 5;
    const int lane = tid & 31;
    const int lq   = lane >> 2;
    const int lr   = lane & 3;

    // stage A = [nodes || agg], 128 x 256, as tf32
    for (int i = tid; i < TILE_M * (2 * D / 4); i += 256) {
        int r  = i >> 6;            // 64 float4 per row
        int c4 = (i & 63) * 4;
        float4 v = make_float4(0.f, 0.f, 0.f, 0.f);
        int gr = row0 + r;
        if (gr < N_NODES) {
            if (c4 < D) v = *reinterpret_cast<const float4*>(nodes + (size_t)gr * D + c4);
            else        v = *reinterpret_cast<const float4*>(g_agg + (size_t)gr * D + (c4 - D));
        }
        uint32_t* dst = sA + r * LDH + c4;
        dst[0] = f2tf(v.x); dst[1] = f2tf(v.y); dst[2] = f2tf(v.z); dst[3] = f2tf(v.w);
    }
    __syncthreads();

    // ---- GEMM1: hidden[128x256] = relu(A @ Wn1 + bn1); warp owns 32 cols
    float acc1[8][4][4];
    #pragma unroll
    for (int i = 0; i < 8; ++i)
        #pragma unroll
        for (int j = 0; j < 4; ++j)
            #pragma unroll
            for (int k = 0; k < 4; ++k) acc1[i][j][k] = 0.f;

    {
        const int ncol0 = warp * 32;
        #pragma unroll 1
        for (int kt = 0; kt < (2 * D) / 8; ++kt) {     // 32 k-tiles
            const int kb = kt * 8;
            uint32_t b[4][2];
            #pragma unroll
            for (int ct = 0; ct < 4; ++ct) {
                int n = ncol0 + ct * 8 + lq;
                b[ct][0] = f2tf(__ldg(Wn1 + (size_t)(kb + lr) * H + n));
                b[ct][1] = f2tf(__ldg(Wn1 + (size_t)(kb + 4 + lr) * H + n));
            }
            #pragma unroll
            for (int rt = 0; rt < 8; ++rt) {
                const uint32_t* base = sA + (rt * 16 + lq) * LDH + kb + lr;
                uint32_t a[4];
                a[0] = base[0];
                a[1] = base[8 * LDH];
                a[2] = base[4];
                a[3] = base[8 * LDH + 4];
                #pragma unroll
                for (int ct = 0; ct < 4; ++ct) mma_tf32(acc1[rt][ct], a, b[ct]);
            }
        }
    }
    __syncthreads();   // everyone done READING sA

    // write hidden (bias + relu, tf32) over sA
    {
        const int ncol0 = warp * 32;
        #pragma unroll
        for (int rt = 0; rt < 8; ++rt) {
            #pragma unroll
            for (int ct = 0; ct < 4; ++ct) {
                int r = rt * 16 + lq;
                int c = ncol0 + ct * 8 + lr * 2;
                float b0 = __ldg(bn1 + c), b1 = __ldg(bn1 + c + 1);
                sA[r * LDH + c]           = f2tf(fmaxf(acc1[rt][ct][0] + b0, 0.f));
                sA[r * LDH + c + 1]       = f2tf(fmaxf(acc1[rt][ct][1] + b1, 0.f));
                sA[(r + 8) * LDH + c]     = f2tf(fmaxf(acc1[rt][ct][2] + b0, 0.f));
                sA[(r + 8) * LDH + c + 1] = f2tf(fmaxf(acc1[rt][ct][3] + b1, 0.f));
            }
        }
    }
    __syncthreads();

    // ---- GEMM2: upd[128x128] = hidden @ Wn2; out = nodes + upd + bn2
    {
        const int wr = warp >> 2;
        const int wc = warp & 3;
        float acc[4][4][4];
        #pragma unroll
        for (int i = 0; i < 4; ++i)
            #pragma unroll
            for (int j = 0; j < 4; ++j)
                #pragma unroll
                for (int k = 0; k < 4; ++k) acc[i][j][k] = 0.f;

        #pragma unroll 1
        for (int kt = 0; kt < H / 8; ++kt) {
            const int kb = kt * 8;
            uint32_t b[4][2];
            #pragma unroll
            for (int ct = 0; ct < 4; ++ct) {
                int n = wc * 32 + ct * 8 + lq;
                b[ct][0] = f2tf(__ldg(Wn2 + (size_t)(kb + lr) * D + n));
                b[ct][1] = f2tf(__ldg(Wn2 + (size_t)(kb + 4 + lr) * D + n));
            }
            #pragma unroll
            for (int rt = 0; rt < 4; ++rt) {
                const uint32_t* base = sA + (wr * 64 + rt * 16 + lq) * LDH + kb + lr;
                uint32_t a[4];
                a[0] = base[0];
                a[1] = base[8 * LDH];
                a[2] = base[4];
                a[3] = base[8 * LDH + 4];
                #pragma unroll
                for (int ct = 0; ct < 4; ++ct) mma_tf32(acc[rt][ct], a, b[ct]);
            }
        }
        #pragma unroll
        for (int rt = 0; rt < 4; ++rt) {
            #pragma unroll
            for (int ct = 0; ct < 4; ++ct) {
                int r = wr * 64 + rt * 16 + lq;
                int c = wc * 32 + ct * 8 + lr * 2;
                float b0 = __ldg(bn2 + c), b1 = __ldg(bn2 + c + 1);
                int gr = row0 + r;
                if (gr < N_NODES) {
                    float2 xn = *reinterpret_cast<const float2*>(nodes + (size_t)gr * D + c);
                    float2 v  = make_float2(xn.x + acc[rt][ct][0] + b0,
                                            xn.y + acc[rt][ct][1] + b1);
                    *reinterpret_cast<float2*>(out + (size_t)gr * D + c) = v;
                }
                int gr2 = gr + 8;
                if (gr2 < N_NODES) {
                    float2 xn = *reinterpret_cast<const float2*>(nodes + (size_t)gr2 * D + c);
                    float2 v  = make_float2(xn.x + acc[rt][ct][2] + b0,
                                            xn.y + acc[rt][ct][3] + b1);
                    *reinterpret_cast<float2*>(out + (size_t)gr2 * D + c) = v;
                }
            }
        }
    }
}

// ---------------------------------------------------------------------------
// launch
// ---------------------------------------------------------------------------
extern "C" void kernel_launch(void* const* d_in, const int* in_sizes, int n_in,
                              void* d_out, int out_size)
{
    const float* nodes     = (const float*)d_in[0];
    const int*   senders   = (const int*)  d_in[1];
    const int*   receivers = (const int*)  d_in[2];
    const float* Wm1 = (const float*)d_in[3];
    const float* bm1 = (const float*)d_in[4];
    const float* Wm2 = (const float*)d_in[5];
    const float* bm2 = (const float*)d_in[6];
    const float* Wn1 = (const float*)d_in[7];
    const float* bn1 = (const float*)d_in[8];
    const float* Wn2 = (const float*)d_in[9];
    const float* bn2 = (const float*)d_in[10];
    float* out = (float*)d_out;

    const int SMEM1 = (TILE_M * LDX + TILE_M * LDH) * 4;   // 200704 B
    const int SMEM3 = (TILE_M * LDH) * 4;                  // 133120 B
    cudaFuncSetAttribute(msg_mlp_kernel,  cudaFuncAttributeMaxDynamicSharedMemorySize, SMEM1);
    cudaFuncSetAttribute(node_mlp_kernel, cudaFuncAttributeMaxDynamicSharedMemorySize, SMEM3);

    // agg = 0 (independent of msg kernel; same stream keeps ordering trivial)
    {
        int n4 = N_NODES * D / 4;
        zero_agg_kernel<<<(n4 + 255) / 256, 256>>>();
    }

    // m = MLP1(nodes)
    msg_mlp_kernel<<<NTILES, 256, SMEM1>>>(nodes, Wm1, bm1, Wm2, bm2);

    // agg[recv] += m[send]
    {
        long long threads = (long long)N_EDGES * 32;
        int blocks = (int)((threads + 255) / 256);
        scatter_kernel<<<blocks, 256>>>(senders, receivers);
    }

    // out = nodes + MLP2([nodes||agg])
    node_mlp_kernel<<<NTILES, 256, SMEM3>>>(nodes, Wn1, bn1, Wn2, bn2, out);
}